// round 1
// baseline (speedup 1.0000x reference)
#include <cuda_runtime.h>
#include <cuda_bf16.h>
#include <cstdint>

// Problem constants
#define B_    4
#define S_    2048
#define H_    8
#define DK_   16
#define DM_   128
#define BH_   (B_*H_)       // 32
#define D_    32            // folded qk head dim: [q*scale, pos_q]
#define DV_   16

// Scratch (static device arrays: no allocation allowed)
__device__ float Qp_d[(size_t)BH_ * S_ * D_];   // [bh][s][32]      row-major
__device__ float Kp_d[(size_t)BH_ * D_ * S_];   // [bh][32][s]      transposed
__device__ float Vp_d[(size_t)BH_ * DV_ * S_];  // [bh][16][s]      transposed
__device__ float Od_d[(size_t)BH_ * S_ * DV_];  // [bh][s][16]

// ---------------------------------------------------------------------------
// Kernel 1: fused projections.
//   p=0: query @ W0^T *0.25 -> Qp[...,0:16]
//   p=1: pos   @ W0^T       -> Qp[...,16:32]
//   p=2: key   @ W1^T       -> Kp[...,0:16]   (transposed store)
//   p=3: pos   @ W1^T       -> Kp[...,16:32]  (transposed store)
//   p=4: value @ W2^T       -> Vp             (transposed store)
// Tile: 64 rows x 128 out-cols, k-chunks of 32. 256 threads, frag 4x8.
// ---------------------------------------------------------------------------
__global__ void __launch_bounds__(256) proj_kernel(
    const float* __restrict__ query, const float* __restrict__ key,
    const float* __restrict__ value, const float* __restrict__ pos,
    const float* __restrict__ W0, const float* __restrict__ b0,
    const float* __restrict__ W1, const float* __restrict__ b1,
    const float* __restrict__ W2, const float* __restrict__ b2)
{
    const int p = blockIdx.y;
    const float* X = (p == 0) ? query : (p == 1 || p == 3) ? pos : (p == 2) ? key : value;
    const float* W = (p < 2) ? W0 : (p < 4) ? W1 : W2;
    const float* bias = (p < 2) ? b0 : (p < 4) ? b1 : b2;

    const int row0 = blockIdx.x * 64;
    __shared__ float Xs[64 * 33];
    __shared__ float Ws[128 * 33];

    const int tid = threadIdx.x;
    const int tx = tid & 15;      // out-col group (cols o = tx + 16*j)
    const int ty = tid >> 4;      // row group (rows r = ty*4 + i)

    float acc[4][8];
#pragma unroll
    for (int i = 0; i < 4; i++)
#pragma unroll
        for (int j = 0; j < 8; j++) acc[i][j] = 0.f;

    for (int kc = 0; kc < 4; kc++) {
        __syncthreads();
        for (int e = tid; e < 2048; e += 256)
            Xs[(e >> 5) * 33 + (e & 31)] = X[(size_t)(row0 + (e >> 5)) * 128 + kc * 32 + (e & 31)];
        for (int e = tid; e < 4096; e += 256)
            Ws[(e >> 5) * 33 + (e & 31)] = W[(size_t)(e >> 5) * 128 + kc * 32 + (e & 31)];
        __syncthreads();

#pragma unroll 4
        for (int kk = 0; kk < 32; kk++) {
            float a[4], b[8];
#pragma unroll
            for (int i = 0; i < 4; i++) a[i] = Xs[(ty * 4 + i) * 33 + kk];
#pragma unroll
            for (int j = 0; j < 8; j++) b[j] = Ws[(tx + 16 * j) * 33 + kk];
#pragma unroll
            for (int i = 0; i < 4; i++)
#pragma unroll
                for (int j = 0; j < 8; j++) acc[i][j] = fmaf(a[i], b[j], acc[i][j]);
        }
    }

#pragma unroll
    for (int i = 0; i < 4; i++) {
        const int row = row0 + ty * 4 + i;
        const int bb = row >> 11;        // row / 2048
        const int s  = row & 2047;
#pragma unroll
        for (int j = 0; j < 8; j++) {
            const int o = tx + 16 * j;
            const int h = o >> 4, dd = o & 15;
            float y = acc[i][j] + bias[o];
            switch (p) {
                case 0: Qp_d[(((size_t)bb * H_ + h) * S_ + s) * D_ + dd]        = 0.25f * y; break;
                case 1: Qp_d[(((size_t)bb * H_ + h) * S_ + s) * D_ + 16 + dd]   = y;         break;
                case 2: Kp_d[(((size_t)bb * H_ + h) * D_ + dd) * S_ + s]        = y;         break;
                case 3: Kp_d[(((size_t)bb * H_ + h) * D_ + 16 + dd) * S_ + s]   = y;         break;
                default: Vp_d[(((size_t)bb * H_ + h) * DV_ + dd) * S_ + s]      = y;         break;
            }
        }
    }
}

// ---------------------------------------------------------------------------
// Kernel 2: flash attention, fp32, head dim 32 (qk) / 16 (v).
// Grid: (16 q-tiles, 32 bh). Block: 256 threads as 16(ty: row grp) x 16(tx: col grp).
// Q tile 128 rows (rows r = ty + 16*i), K tile 128 keys (cols c = tx + 16*j).
// Each thread: S frag 8x8 in regs; partial O (8 rows x 16 v-cols) over OWN keys,
// reduced across tx lanes (shfl, 16-wide) once at the end. Row max reduced per tile.
// Smem layouts chosen conflict-free: Qs padded stride 33; Ks/Vs transposed.
// ---------------------------------------------------------------------------
__global__ void __launch_bounds__(256, 1) flash_kernel()
{
    const int qt = blockIdx.x;
    const int bh = blockIdx.y;

    __shared__ float Qs[128 * 33];   // [row][d], padded
    __shared__ float Ks[32 * 128];   // [d][key]
    __shared__ float Vs[16 * 128];   // [vc][key]

    const int tid = threadIdx.x;
    const int tx = tid & 15;
    const int ty = tid >> 4;

    // Load Q tile (128 x 32)
    const float* Qb = Qp_d + ((size_t)bh * S_ + qt * 128) * D_;
    for (int e = tid; e < 4096; e += 256)
        Qs[(e >> 5) * 33 + (e & 31)] = Qb[e];

    const float4* Kg4 = (const float4*)(Kp_d + (size_t)bh * D_ * S_);
    const float4* Vg4 = (const float4*)(Vp_d + (size_t)bh * DV_ * S_);

    float m[8], lp[8], Oa[8][16];
#pragma unroll
    for (int i = 0; i < 8; i++) {
        m[i] = -1e30f; lp[i] = 0.f;
#pragma unroll
        for (int c = 0; c < 16; c++) Oa[i][c] = 0.f;
    }

    for (int kt = 0; kt < S_ / 128; kt++) {
        __syncthreads();
        // K tile: 32 rows (d) x 128 keys = 1024 float4/4
#pragma unroll
        for (int e = tid; e < 1024; e += 256)
            ((float4*)Ks)[e] = Kg4[(size_t)(e >> 5) * 512 + kt * 32 + (e & 31)];
#pragma unroll
        for (int e = tid; e < 512; e += 256)
            ((float4*)Vs)[e] = Vg4[(size_t)(e >> 5) * 512 + kt * 32 + (e & 31)];
        __syncthreads();

        // S fragment: rows (ty+16i), cols (tx+16j)
        float Sf[8][8];
#pragma unroll
        for (int i = 0; i < 8; i++)
#pragma unroll
            for (int j = 0; j < 8; j++) Sf[i][j] = 0.f;

#pragma unroll 4
        for (int d = 0; d < 32; d++) {
            float a[8], b[8];
#pragma unroll
            for (int i = 0; i < 8; i++) a[i] = Qs[(ty + 16 * i) * 33 + d];
#pragma unroll
            for (int j = 0; j < 8; j++) b[j] = Ks[d * 128 + tx + 16 * j];
#pragma unroll
            for (int i = 0; i < 8; i++)
#pragma unroll
                for (int j = 0; j < 8; j++) Sf[i][j] = fmaf(a[i], b[j], Sf[i][j]);
        }

        // Row max (local over 8 cols, then across the 16 tx lanes)
        float mt[8];
#pragma unroll
        for (int i = 0; i < 8; i++) {
            float v = Sf[i][0];
#pragma unroll
            for (int j = 1; j < 8; j++) v = fmaxf(v, Sf[i][j]);
            mt[i] = v;
        }
#pragma unroll
        for (int off = 8; off; off >>= 1)
#pragma unroll
            for (int i = 0; i < 8; i++)
                mt[i] = fmaxf(mt[i], __shfl_xor_sync(0xffffffffu, mt[i], off));

        // Online softmax update
#pragma unroll
        for (int i = 0; i < 8; i++) {
            float mn = fmaxf(m[i], mt[i]);
            float corr = __expf(m[i] - mn);
            m[i] = mn;
            lp[i] *= corr;
#pragma unroll
            for (int c = 0; c < 16; c++) Oa[i][c] *= corr;
            float rs = 0.f;
#pragma unroll
            for (int j = 0; j < 8; j++) {
                float e = __expf(Sf[i][j] - mn);
                Sf[i][j] = e;
                rs += e;
            }
            lp[i] += rs;
        }

        // PV: accumulate this thread's 8 keys into its partial O
#pragma unroll
        for (int j = 0; j < 8; j++) {
            float vv[16];
#pragma unroll
            for (int c = 0; c < 16; c++) vv[c] = Vs[c * 128 + tx + 16 * j];
#pragma unroll
            for (int i = 0; i < 8; i++)
#pragma unroll
                for (int c = 0; c < 16; c++)
                    Oa[i][c] = fmaf(Sf[i][j], vv[c], Oa[i][c]);
        }
    }

    // Final reduction across the 16 tx lanes sharing each row
#pragma unroll
    for (int off = 8; off; off >>= 1) {
#pragma unroll
        for (int i = 0; i < 8; i++) {
            lp[i] += __shfl_xor_sync(0xffffffffu, lp[i], off);
#pragma unroll
            for (int c = 0; c < 16; c++)
                Oa[i][c] += __shfl_xor_sync(0xffffffffu, Oa[i][c], off);
        }
    }

    if (tx == 0) {
#pragma unroll
        for (int i = 0; i < 8; i++) {
            float inv = 1.0f / lp[i];
            int s = qt * 128 + ty + 16 * i;
            float4* dst = (float4*)(Od_d + ((size_t)bh * S_ + s) * DV_);
            dst[0] = make_float4(Oa[i][0] * inv,  Oa[i][1] * inv,  Oa[i][2] * inv,  Oa[i][3] * inv);
            dst[1] = make_float4(Oa[i][4] * inv,  Oa[i][5] * inv,  Oa[i][6] * inv,  Oa[i][7] * inv);
            dst[2] = make_float4(Oa[i][8] * inv,  Oa[i][9] * inv,  Oa[i][10] * inv, Oa[i][11] * inv);
            dst[3] = make_float4(Oa[i][12] * inv, Oa[i][13] * inv, Oa[i][14] * inv, Oa[i][15] * inv);
        }
    }
}

// ---------------------------------------------------------------------------
// Kernel 3: output projection.  out = concat_heads(O) @ Wo^T + bo
// Same tiling as kernel 1; X gathered from Od_d.
// ---------------------------------------------------------------------------
__global__ void __launch_bounds__(256) outproj_kernel(
    const float* __restrict__ Wo, const float* __restrict__ bo,
    float* __restrict__ out)
{
    const int row0 = blockIdx.x * 64;
    const int bb = row0 >> 11;
    const int s0 = row0 & 2047;

    __shared__ float Xs[64 * 33];
    __shared__ float Ws[128 * 33];

    const int tid = threadIdx.x;
    const int tx = tid & 15;
    const int ty = tid >> 4;

    float acc[4][8];
#pragma unroll
    for (int i = 0; i < 4; i++)
#pragma unroll
        for (int j = 0; j < 8; j++) acc[i][j] = 0.f;

    for (int kc = 0; kc < 4; kc++) {
        __syncthreads();
        for (int e = tid; e < 2048; e += 256) {
            const int r = e >> 5, cc = e & 31;
            const int col = kc * 32 + cc;
            const int h = col >> 4, dd = col & 15;
            Xs[r * 33 + cc] = Od_d[(((size_t)bb * H_ + h) * S_ + s0 + r) * DV_ + dd];
        }
        for (int e = tid; e < 4096; e += 256)
            Ws[(e >> 5) * 33 + (e & 31)] = Wo[(size_t)(e >> 5) * 128 + kc * 32 + (e & 31)];
        __syncthreads();

#pragma unroll 4
        for (int kk = 0; kk < 32; kk++) {
            float a[4], b[8];
#pragma unroll
            for (int i = 0; i < 4; i++) a[i] = Xs[(ty * 4 + i) * 33 + kk];
#pragma unroll
            for (int j = 0; j < 8; j++) b[j] = Ws[(tx + 16 * j) * 33 + kk];
#pragma unroll
            for (int i = 0; i < 4; i++)
#pragma unroll
                for (int j = 0; j < 8; j++) acc[i][j] = fmaf(a[i], b[j], acc[i][j]);
        }
    }

#pragma unroll
    for (int i = 0; i < 4; i++) {
        const int row = row0 + ty * 4 + i;
#pragma unroll
        for (int j = 0; j < 8; j++) {
            const int o = tx + 16 * j;
            out[(size_t)row * 128 + o] = acc[i][j] + bo[o];
        }
    }
}

// ---------------------------------------------------------------------------
extern "C" void kernel_launch(void* const* d_in, const int* in_sizes, int n_in,
                              void* d_out, int out_size)
{
    const float* query = (const float*)d_in[0];
    const float* key   = (const float*)d_in[1];
    const float* value = (const float*)d_in[2];
    const float* pos   = (const float*)d_in[3];
    const float* W0    = (const float*)d_in[4];
    const float* b0    = (const float*)d_in[5];
    const float* W1    = (const float*)d_in[6];
    const float* b1    = (const float*)d_in[7];
    const float* W2    = (const float*)d_in[8];
    const float* b2    = (const float*)d_in[9];
    const float* Wo    = (const float*)d_in[10];
    const float* bo    = (const float*)d_in[11];
    float* out = (float*)d_out;

    proj_kernel<<<dim3((B_ * S_) / 64, 5), 256>>>(query, key, value, pos,
                                                  W0, b0, W1, b1, W2, b2);
    flash_kernel<<<dim3(S_ / 128, BH_), 256>>>();
    outproj_kernel<<<(B_ * S_) / 64, 256>>>(Wo, bo, out);
}

// round 3
// speedup vs baseline: 2.1615x; 2.1615x over previous
#include <cuda_runtime.h>
#include <cuda_fp16.h>
#include <cstdint>

// Problem constants
#define B_    4
#define S_    2048
#define H_    8
#define BH_   (B_*H_)       // 32

// Packed split-fp16 intermediates (static device scratch)
__device__ __align__(256) __half Qpack_d[(size_t)BH_ * S_ * 64];  // [bh][s][Qh(32)|Ql(32)]
__device__ __align__(256) __half Kpack_d[(size_t)BH_ * S_ * 64];  // [bh][key][Kh(32)|Kl(32)]
__device__ __align__(256) __half Vh_d[(size_t)BH_ * 16 * S_];     // [bh][vd][key]
__device__ __align__(256) __half Vl_d[(size_t)BH_ * 16 * S_];
__device__ __align__(256) float  Od_d[(size_t)BH_ * S_ * 16];     // [bh][s][16]

// ---------------------------------------------------------------------------
// PTX helpers (baseline features only — compute_103-safe)
// ---------------------------------------------------------------------------
__device__ __forceinline__ uint32_t smem_u32(const void* p) {
    uint32_t a;
    asm("{ .reg .u64 t; cvta.to.shared.u64 t, %1; cvt.u32.u64 %0, t; }" : "=r"(a) : "l"(p));
    return a;
}
__device__ __forceinline__ void cp16(uint32_t d, const void* s) {
    asm volatile("cp.async.cg.shared.global [%0], [%1], 16;" :: "r"(d), "l"(s));
}
#define CP_COMMIT() asm volatile("cp.async.commit_group;" ::: "memory")
#define CP_WAIT1()  asm volatile("cp.async.wait_group 1;" ::: "memory")

__device__ __forceinline__ void ldm4(uint32_t* r, uint32_t addr) {
    asm volatile("ldmatrix.sync.aligned.m8n8.x4.shared.b16 {%0,%1,%2,%3}, [%4];"
        : "=r"(r[0]), "=r"(r[1]), "=r"(r[2]), "=r"(r[3]) : "r"(addr));
}
__device__ __forceinline__ void mma16816(float* d, const uint32_t* a, const uint32_t* b) {
    asm volatile("mma.sync.aligned.m16n8k16.row.col.f32.f16.f16.f32 "
        "{%0,%1,%2,%3}, {%4,%5,%6,%7}, {%8,%9}, {%0,%1,%2,%3};"
        : "+f"(d[0]), "+f"(d[1]), "+f"(d[2]), "+f"(d[3])
        : "r"(a[0]), "r"(a[1]), "r"(a[2]), "r"(a[3]), "r"(b[0]), "r"(b[1]));
}

#define SWZ(x) ((x) ^ (((x) >> 3) & 0x70))

// ---------------------------------------------------------------------------
// Kernel 1: fused fp32 projections -> split-fp16 packed outputs.
//   p=0: query@W0^T *0.25 -> Q dims 0-15     p=1: pos@W0^T -> Q dims 16-31
//   p=2: key  @W1^T       -> K dims 0-15     p=3: pos@W1^T -> K dims 16-31
//   p=4: value@W2^T       -> V (transposed, hi/lo)
// ---------------------------------------------------------------------------
__global__ void __launch_bounds__(256) proj_kernel(
    const float* __restrict__ query, const float* __restrict__ key,
    const float* __restrict__ value, const float* __restrict__ pos,
    const float* __restrict__ W0, const float* __restrict__ b0,
    const float* __restrict__ W1, const float* __restrict__ b1,
    const float* __restrict__ W2, const float* __restrict__ b2)
{
    const int p = blockIdx.y;
    const float* X = (p == 0) ? query : (p == 1 || p == 3) ? pos : (p == 2) ? key : value;
    const float* W = (p < 2) ? W0 : (p < 4) ? W1 : W2;
    const float* bias = (p < 2) ? b0 : (p < 4) ? b1 : b2;

    const int row0 = blockIdx.x * 64;
    __shared__ float Xs[64 * 33];
    __shared__ float Ws[128 * 33];

    const int tid = threadIdx.x;
    const int tx = tid & 15;
    const int ty = tid >> 4;

    float acc[4][8];
#pragma unroll
    for (int i = 0; i < 4; i++)
#pragma unroll
        for (int j = 0; j < 8; j++) acc[i][j] = 0.f;

    for (int kc = 0; kc < 4; kc++) {
        __syncthreads();
        for (int e = tid; e < 2048; e += 256)
            Xs[(e >> 5) * 33 + (e & 31)] = X[(size_t)(row0 + (e >> 5)) * 128 + kc * 32 + (e & 31)];
        for (int e = tid; e < 4096; e += 256)
            Ws[(e >> 5) * 33 + (e & 31)] = W[(size_t)(e >> 5) * 128 + kc * 32 + (e & 31)];
        __syncthreads();

#pragma unroll 4
        for (int kk = 0; kk < 32; kk++) {
            float a[4], b[8];
#pragma unroll
            for (int i = 0; i < 4; i++) a[i] = Xs[(ty * 4 + i) * 33 + kk];
#pragma unroll
            for (int j = 0; j < 8; j++) b[j] = Ws[(tx + 16 * j) * 33 + kk];
#pragma unroll
            for (int i = 0; i < 4; i++)
#pragma unroll
                for (int j = 0; j < 8; j++) acc[i][j] = fmaf(a[i], b[j], acc[i][j]);
        }
    }

#pragma unroll
    for (int i = 0; i < 4; i++) {
        const int row = row0 + ty * 4 + i;
        const int bb = row >> 11;
        const int s  = row & 2047;
#pragma unroll
        for (int j = 0; j < 8; j++) {
            const int o = tx + 16 * j;
            const int hh = o >> 4, dd = o & 15;
            float y = acc[i][j] + bias[o];
            if (p == 0) y *= 0.25f;               // fold softmax scale into q
            __half hi = __float2half_rn(y);
            __half lo = __float2half_rn(y - __half2float(hi));
            const size_t bhrow = ((size_t)(bb * H_ + hh) * S_ + s);
            switch (p) {
                case 0: Qpack_d[bhrow * 64 + dd]      = hi; Qpack_d[bhrow * 64 + 32 + dd] = lo; break;
                case 1: Qpack_d[bhrow * 64 + 16 + dd] = hi; Qpack_d[bhrow * 64 + 48 + dd] = lo; break;
                case 2: Kpack_d[bhrow * 64 + dd]      = hi; Kpack_d[bhrow * 64 + 32 + dd] = lo; break;
                case 3: Kpack_d[bhrow * 64 + 16 + dd] = hi; Kpack_d[bhrow * 64 + 48 + dd] = lo; break;
                default: {
                    const size_t vi = ((size_t)(bb * H_ + hh) * 16 + dd) * S_ + s;
                    Vh_d[vi] = hi; Vl_d[vi] = lo;
                } break;
            }
        }
    }
}

// ---------------------------------------------------------------------------
// Kernel 2: HMMA flash attention (mma.sync m16n8k16, split-fp16 x3 chains).
// Block = (qt 128 rows, bh), 256 threads = 8 warps x 16 rows.
// Per 64-key tile, per warp: S(16x64) = QhKh+QhKl+QlKh (48 mma) -> in-reg
// online softmax -> P frags = S C-frags recast -> O += PhVh+PlVh+PhVl (24 mma).
// ---------------------------------------------------------------------------
__global__ void __launch_bounds__(256, 2) flash_kernel()
{
    __shared__ __align__(1024) char Qs[16384];       // 128 rows x [Qh|Ql] 128B
    __shared__ __align__(1024) char Ks[2][8192];     // 64 keys x [Kh|Kl] 128B
    __shared__ __align__(1024) char Vhs[2][2048];    // 16 vd x 64 keys fp16
    __shared__ __align__(1024) char Vls[2][2048];

    const int qt = blockIdx.x;
    const int bh = blockIdx.y;
    const int tid  = threadIdx.x;
    const int warp = tid >> 5;
    const int lane = tid & 31;
    const int grp  = lane >> 3;     // ldmatrix address group
    const int wi   = lane & 7;

    const uint32_t qs = smem_u32(Qs);
    const uint32_t ksb[2] = { smem_u32(Ks[0]),  smem_u32(Ks[1]) };
    const uint32_t vhb[2] = { smem_u32(Vhs[0]), smem_u32(Vhs[1]) };
    const uint32_t vlb[2] = { smem_u32(Vls[0]), smem_u32(Vls[1]) };

    // ---- prologue: Q tile + kv tiles 0,1 via cp.async ----
    {
        const __half* Qg = Qpack_d + ((size_t)bh * S_ + (size_t)qt * 128) * 64;
#pragma unroll
        for (int i = 0; i < 4; i++) {
            int e = tid + i * 256;
            cp16(qs + SWZ((e >> 3) * 128 + (e & 7) * 16), Qg + (size_t)e * 8);
        }
    }
#pragma unroll
    for (int pre = 0; pre < 2; pre++) {
        const __half* Kg = Kpack_d + ((size_t)bh * S_ + (size_t)pre * 64) * 64;
#pragma unroll
        for (int i = 0; i < 2; i++) {
            int e = tid + i * 256;
            cp16(ksb[pre] + SWZ((e >> 3) * 128 + (e & 7) * 16), Kg + (size_t)e * 8);
        }
        if (tid < 128) {
            int r = tid >> 3, c = tid & 7;
            cp16(vhb[pre] + SWZ(r * 128 + c * 16),
                 Vh_d + ((size_t)bh * 16 + r) * S_ + (size_t)pre * 64 + c * 8);
        } else {
            int t2 = tid - 128;
            int r = t2 >> 3, c = t2 & 7;
            cp16(vlb[pre] + SWZ(r * 128 + c * 16),
                 Vl_d + ((size_t)bh * 16 + r) * S_ + (size_t)pre * 64 + c * 8);
        }
        CP_COMMIT();
    }

    CP_WAIT1();            // Q + tile0 resident
    __syncthreads();

    // ---- Q A-fragments, loaded once: t=0,1 -> Qh dims 0-31; t=2,3 -> Ql ----
    uint32_t Aq[4][4];
#pragma unroll
    for (int t = 0; t < 4; t++) {
        const int row = warp * 16 + (grp & 1) * 8 + wi;
        const int ch  = t * 16 + (grp >> 1) * 8;
        ldm4(Aq[t], qs + SWZ(row * 128 + ch * 2));
    }

    float m0 = -1e30f, m1 = -1e30f, l0 = 0.f, l1 = 0.f;
    float Oc[2][4];
#pragma unroll
    for (int nb = 0; nb < 2; nb++)
#pragma unroll
        for (int j = 0; j < 4; j++) Oc[nb][j] = 0.f;

    for (int kt = 0; kt < S_ / 64; kt++) {
        const int buf = kt & 1;
        const uint32_t kss = ksb[buf];

        // --- S = Qh*Kh + Ql*Kh + Qh*Kl ---
        float Sc[8][4];
#pragma unroll
        for (int nb = 0; nb < 8; nb++)
#pragma unroll
            for (int j = 0; j < 4; j++) Sc[nb][j] = 0.f;

#pragma unroll
        for (int t = 0; t < 2; t++) {
#pragma unroll
            for (int p = 0; p < 4; p++) {
                const int key = p * 16 + (grp >> 1) * 8 + wi;
                uint32_t kb[4];
                // Kh: cols t*16 .. (+8 via grp&1)
                ldm4(kb, kss + SWZ(key * 128 + (t * 16 + (grp & 1) * 8) * 2));
                mma16816(Sc[2 * p],     Aq[t],     kb);
                mma16816(Sc[2 * p + 1], Aq[t],     kb + 2);
                mma16816(Sc[2 * p],     Aq[t + 2], kb);
                mma16816(Sc[2 * p + 1], Aq[t + 2], kb + 2);
                // Kl: cols 32 + t*16
                ldm4(kb, kss + SWZ(key * 128 + (32 + t * 16 + (grp & 1) * 8) * 2));
                mma16816(Sc[2 * p],     Aq[t], kb);
                mma16816(Sc[2 * p + 1], Aq[t], kb + 2);
            }
        }

        // --- online softmax (rows l/4 and l/4+8; quad = lanes sharing l/4) ---
        float mx0 = -1e30f, mx1 = -1e30f;
#pragma unroll
        for (int nb = 0; nb < 8; nb++) {
            mx0 = fmaxf(mx0, fmaxf(Sc[nb][0], Sc[nb][1]));
            mx1 = fmaxf(mx1, fmaxf(Sc[nb][2], Sc[nb][3]));
        }
        mx0 = fmaxf(mx0, __shfl_xor_sync(0xffffffffu, mx0, 1));
        mx0 = fmaxf(mx0, __shfl_xor_sync(0xffffffffu, mx0, 2));
        mx1 = fmaxf(mx1, __shfl_xor_sync(0xffffffffu, mx1, 1));
        mx1 = fmaxf(mx1, __shfl_xor_sync(0xffffffffu, mx1, 2));

        const float mn0 = fmaxf(m0, mx0), mn1 = fmaxf(m1, mx1);
        const float c0 = __expf(m0 - mn0), c1 = __expf(m1 - mn1);
        m0 = mn0; m1 = mn1;

        float s0 = 0.f, s1 = 0.f;
#pragma unroll
        for (int nb = 0; nb < 8; nb++) {
            Sc[nb][0] = __expf(Sc[nb][0] - mn0);
            Sc[nb][1] = __expf(Sc[nb][1] - mn0);
            Sc[nb][2] = __expf(Sc[nb][2] - mn1);
            Sc[nb][3] = __expf(Sc[nb][3] - mn1);
            s0 += Sc[nb][0] + Sc[nb][1];
            s1 += Sc[nb][2] + Sc[nb][3];
        }
        s0 += __shfl_xor_sync(0xffffffffu, s0, 1);
        s0 += __shfl_xor_sync(0xffffffffu, s0, 2);
        s1 += __shfl_xor_sync(0xffffffffu, s1, 1);
        s1 += __shfl_xor_sync(0xffffffffu, s1, 2);
        l0 = l0 * c0 + s0;
        l1 = l1 * c1 + s1;

#pragma unroll
        for (int nb = 0; nb < 2; nb++) {
            Oc[nb][0] *= c0; Oc[nb][1] *= c0;
            Oc[nb][2] *= c1; Oc[nb][3] *= c1;
        }

        // --- O += Ph*Vh + Pl*Vh + Ph*Vl ---
        const int vrow = (grp >> 1) * 8 + wi;
#pragma unroll
        for (int k2 = 0; k2 < 4; k2++) {
            uint32_t Pa[4], Pla[4];
#pragma unroll
            for (int h = 0; h < 2; h++) {        // nblocks 2k2, 2k2+1
                const float e0 = Sc[2 * k2 + h][0], e1 = Sc[2 * k2 + h][1];
                const float e2 = Sc[2 * k2 + h][2], e3 = Sc[2 * k2 + h][3];
                __half2 h01 = __floats2half2_rn(e0, e1);
                __half2 h23 = __floats2half2_rn(e2, e3);
                float2 f01 = __half22float2(h01);
                float2 f23 = __half22float2(h23);
                __half2 l01 = __floats2half2_rn(e0 - f01.x, e1 - f01.y);
                __half2 l23 = __floats2half2_rn(e2 - f23.x, e3 - f23.y);
                Pa[2 * h]      = *reinterpret_cast<uint32_t*>(&h01);
                Pa[2 * h + 1]  = *reinterpret_cast<uint32_t*>(&h23);
                Pla[2 * h]     = *reinterpret_cast<uint32_t*>(&l01);
                Pla[2 * h + 1] = *reinterpret_cast<uint32_t*>(&l23);
            }
            const uint32_t voff = SWZ(vrow * 128 + (k2 * 16 + (grp & 1) * 8) * 2);
            uint32_t vb[4];
            ldm4(vb, vhb[buf] + voff);
            mma16816(Oc[0], Pa,  vb);
            mma16816(Oc[1], Pa,  vb + 2);
            mma16816(Oc[0], Pla, vb);
            mma16816(Oc[1], Pla, vb + 2);
            ldm4(vb, vlb[buf] + voff);
            mma16816(Oc[0], Pa, vb);
            mma16816(Oc[1], Pa, vb + 2);
        }

        // --- prefetch tile kt+2 into this buffer ---
        __syncthreads();                          // everyone done reading buf
        if (kt + 2 < S_ / 64) {
            const __half* Kg = Kpack_d + ((size_t)bh * S_ + (size_t)(kt + 2) * 64) * 64;
#pragma unroll
            for (int i = 0; i < 2; i++) {
                int e = tid + i * 256;
                cp16(ksb[buf] + SWZ((e >> 3) * 128 + (e & 7) * 16), Kg + (size_t)e * 8);
            }
            if (tid < 128) {
                int r = tid >> 3, c = tid & 7;
                cp16(vhb[buf] + SWZ(r * 128 + c * 16),
                     Vh_d + ((size_t)bh * 16 + r) * S_ + (size_t)(kt + 2) * 64 + c * 8);
            } else {
                int t2 = tid - 128;
                int r = t2 >> 3, c = t2 & 7;
                cp16(vlb[buf] + SWZ(r * 128 + c * 16),
                     Vl_d + ((size_t)bh * 16 + r) * S_ + (size_t)(kt + 2) * 64 + c * 8);
            }
        }
        CP_COMMIT();
        if (kt + 1 < S_ / 64) {
            CP_WAIT1();                           // next tile resident
            __syncthreads();
        }
    }

    // ---- epilogue: normalize rows, store ----
    {
        const float i0 = 1.0f / l0, i1 = 1.0f / l1;
        const int r0 = qt * 128 + warp * 16 + (lane >> 2);
        const int r1 = r0 + 8;
#pragma unroll
        for (int nb = 0; nb < 2; nb++) {
            const int col = nb * 8 + (lane & 3) * 2;
            float2* d0 = (float2*)(Od_d + ((size_t)bh * S_ + r0) * 16 + col);
            float2* d1 = (float2*)(Od_d + ((size_t)bh * S_ + r1) * 16 + col);
            *d0 = make_float2(Oc[nb][0] * i0, Oc[nb][1] * i0);
            *d1 = make_float2(Oc[nb][2] * i1, Oc[nb][3] * i1);
        }
    }
}

// ---------------------------------------------------------------------------
// Kernel 3: output projection.  out = concat_heads(O) @ Wo^T + bo
// ---------------------------------------------------------------------------
__global__ void __launch_bounds__(256) outproj_kernel(
    const float* __restrict__ Wo, const float* __restrict__ bo,
    float* __restrict__ out)
{
    const int row0 = blockIdx.x * 64;
    const int bb = row0 >> 11;
    const int s0 = row0 & 2047;

    __shared__ float Xs[64 * 33];
    __shared__ float Ws[128 * 33];

    const int tid = threadIdx.x;
    const int tx = tid & 15;
    const int ty = tid >> 4;

    float acc[4][8];
#pragma unroll
    for (int i = 0; i < 4; i++)
#pragma unroll
        for (int j = 0; j < 8; j++) acc[i][j] = 0.f;

    for (int kc = 0; kc < 4; kc++) {
        __syncthreads();
        for (int e = tid; e < 2048; e += 256) {
            const int r = e >> 5, cc = e & 31;
            const int col = kc * 32 + cc;
            const int hh = col >> 4, dd = col & 15;
            Xs[r * 33 + cc] = Od_d[(((size_t)bb * H_ + hh) * S_ + s0 + r) * 16 + dd];
        }
        for (int e = tid; e < 4096; e += 256)
            Ws[(e >> 5) * 33 + (e & 31)] = Wo[(size_t)(e >> 5) * 128 + kc * 32 + (e & 31)];
        __syncthreads();

#pragma unroll 4
        for (int kk = 0; kk < 32; kk++) {
            float a[4], b[8];
#pragma unroll
            for (int i = 0; i < 4; i++) a[i] = Xs[(ty * 4 + i) * 33 + kk];
#pragma unroll
            for (int j = 0; j < 8; j++) b[j] = Ws[(tx + 16 * j) * 33 + kk];
#pragma unroll
            for (int i = 0; i < 4; i++)
#pragma unroll
                for (int j = 0; j < 8; j++) acc[i][j] = fmaf(a[i], b[j], acc[i][j]);
        }
    }

#pragma unroll
    for (int i = 0; i < 4; i++) {
        const int row = row0 + ty * 4 + i;
#pragma unroll
        for (int j = 0; j < 8; j++)
            out[(size_t)row * 128 + tx + 16 * j] = acc[i][j] + bo[tx + 16 * j];
    }
}

// ---------------------------------------------------------------------------
extern "C" void kernel_launch(void* const* d_in, const int* in_sizes, int n_in,
                              void* d_out, int out_size)
{
    const float* query = (const float*)d_in[0];
    const float* key   = (const float*)d_in[1];
    const float* value = (const float*)d_in[2];
    const float* pos   = (const float*)d_in[3];
    const float* W0    = (const float*)d_in[4];
    const float* b0    = (const float*)d_in[5];
    const float* W1    = (const float*)d_in[6];
    const float* b1    = (const float*)d_in[7];
    const float* W2    = (const float*)d_in[8];
    const float* b2    = (const float*)d_in[9];
    const float* Wo    = (const float*)d_in[10];
    const float* bo    = (const float*)d_in[11];
    float* out = (float*)d_out;

    proj_kernel<<<dim3((B_ * S_) / 64, 5), 256>>>(query, key, value, pos,
                                                  W0, b0, W1, b1, W2, b2);
    flash_kernel<<<dim3(S_ / 128, BH_), 256>>>();
    outproj_kernel<<<(B_ * S_) / 64, 256>>>(Wo, bo, out);
}

// round 5
// speedup vs baseline: 2.7391x; 1.2672x over previous
#include <cuda_runtime.h>
#include <cuda_fp16.h>
#include <cstdint>

// Problem constants
#define B_    4
#define S_    2048
#define H_    8
#define BH_   (B_*H_)       // 32

// Packed split-fp16 intermediates (static device scratch)
__device__ __align__(256) __half Qpack_d[(size_t)BH_ * S_ * 64];  // [bh][s][Qh(32)|Ql(32)]
__device__ __align__(256) __half Kpack_d[(size_t)BH_ * S_ * 64];  // [bh][key][Kh(32)|Kl(32)]
__device__ __align__(256) __half Vh_d[(size_t)BH_ * 16 * S_];     // [bh][vd][key]
__device__ __align__(256) __half Vl_d[(size_t)BH_ * 16 * S_];
__device__ __align__(256) float  Od_d[(size_t)BH_ * S_ * 16];     // [bh][s][16]
__device__ __align__(256) __half Wsplit_d[4][128][2][128];        // [w][o][hi/lo][k]

// ---------------------------------------------------------------------------
// PTX helpers (baseline features only — compute_103-safe)
// ---------------------------------------------------------------------------
__device__ __forceinline__ uint32_t smem_u32(const void* p) {
    uint32_t a;
    asm("{ .reg .u64 t; cvta.to.shared.u64 t, %1; cvt.u32.u64 %0, t; }" : "=r"(a) : "l"(p));
    return a;
}
__device__ __forceinline__ void cp16(uint32_t d, const void* s) {
    asm volatile("cp.async.cg.shared.global [%0], [%1], 16;" :: "r"(d), "l"(s));
}
#define CP_COMMIT() asm volatile("cp.async.commit_group;" ::: "memory")
#define CP_WAIT1()  asm volatile("cp.async.wait_group 1;" ::: "memory")
#define CP_WAIT0()  asm volatile("cp.async.wait_group 0;" ::: "memory")

__device__ __forceinline__ void ldm4(uint32_t* r, uint32_t addr) {
    asm volatile("ldmatrix.sync.aligned.m8n8.x4.shared.b16 {%0,%1,%2,%3}, [%4];"
        : "=r"(r[0]), "=r"(r[1]), "=r"(r[2]), "=r"(r[3]) : "r"(addr));
}
__device__ __forceinline__ void mma16816(float* d, const uint32_t* a, const uint32_t* b) {
    asm volatile("mma.sync.aligned.m16n8k16.row.col.f32.f16.f16.f32 "
        "{%0,%1,%2,%3}, {%4,%5,%6,%7}, {%8,%9}, {%0,%1,%2,%3};"
        : "+f"(d[0]), "+f"(d[1]), "+f"(d[2]), "+f"(d[3])
        : "r"(a[0]), "r"(a[1]), "r"(a[2]), "r"(a[3]), "r"(b[0]), "r"(b[1]));
}

#define SWZ(x) ((x) ^ (((x) >> 3) & 0x70))

__device__ __forceinline__ void split2(float x, __half& hi, __half& lo) {
    hi = __float2half_rn(x);
    lo = __float2half_rn(x - __half2float(hi));
}
// CORRECT 32-bit pack of two halves (round-4 bug: __half2_raw.x is ushort)
__device__ __forceinline__ uint32_t pack2(__half a, __half b) {
    __half2 t = __halves2half2(a, b);
    return *reinterpret_cast<uint32_t*>(&t);
}

// ---------------------------------------------------------------------------
// Kernel 0: split W0/W1/W2/Wo into fp16 hi/lo pairs.
// ---------------------------------------------------------------------------
__global__ void __launch_bounds__(256) prep_kernel(
    const float* __restrict__ W0, const float* __restrict__ W1,
    const float* __restrict__ W2, const float* __restrict__ Wo)
{
    const int idx = blockIdx.x * 256 + threadIdx.x;   // 0 .. 65535
    const int w = idx >> 14;
    const int o = (idx >> 7) & 127;
    const int k = idx & 127;
    const float* W = (w == 0) ? W0 : (w == 1) ? W1 : (w == 2) ? W2 : Wo;
    __half hi, lo;
    split2(W[o * 128 + k], hi, lo);
    Wsplit_d[w][o][0][k] = hi;
    Wsplit_d[w][o][1][k] = lo;
}

// ---------------------------------------------------------------------------
// Kernel 1: HMMA projections (split-fp16, 3 chains).
//   p=0: query@W0^T *0.25 -> Q dims 0-15     p=1: pos@W0^T -> Q dims 16-31
//   p=2: key  @W1^T       -> K dims 0-15     p=3: pos@W1^T -> K dims 16-31
//   p=4: value@W2^T       -> V (transposed, hi/lo)
// Block: 64 rows x 128 out-cols, 8 warps (warp = 16 rows x 64 cols). K chunks of 64.
// ---------------------------------------------------------------------------
__global__ void __launch_bounds__(256) proj_kernel(
    const float* __restrict__ query, const float* __restrict__ key,
    const float* __restrict__ value, const float* __restrict__ pos,
    const float* __restrict__ b0, const float* __restrict__ b1,
    const float* __restrict__ b2)
{
    __shared__ __align__(1024) __half Xh[64 * 64];    // 64 rows x 128B
    __shared__ __align__(1024) __half Xl[64 * 64];
    __shared__ __align__(1024) __half Wh[128 * 64];   // 128 o x 128B
    __shared__ __align__(1024) __half Wl[128 * 64];

    const int p = blockIdx.y;
    const float* X = (p == 0) ? query : (p == 1 || p == 3) ? pos : (p == 2) ? key : value;
    const float* bias = (p < 2) ? b0 : (p < 4) ? b1 : b2;
    const int wsel = (p < 2) ? 0 : (p < 4) ? 1 : 2;

    const int row0 = blockIdx.x * 64;
    const int tid  = threadIdx.x;
    const int warp = tid >> 5;
    const int lane = tid & 31;
    const int grp  = lane >> 3;
    const int wi   = lane & 7;

    const uint32_t xh = smem_u32(Xh), xl = smem_u32(Xl);
    const uint32_t wh = smem_u32(Wh), wl = smem_u32(Wl);

    const int mrow0 = (warp >> 1) * 16;     // warp row base within tile
    const int ncol0 = (warp & 1) * 64;      // warp col base

    float C[8][4];
#pragma unroll
    for (int nb = 0; nb < 8; nb++)
#pragma unroll
        for (int j = 0; j < 4; j++) C[nb][j] = 0.f;

    for (int kc = 0; kc < 2; kc++) {
        __syncthreads();
        // W chunk: cp.async fp16 hi/lo, 128 o-rows x 64 k
#pragma unroll
        for (int it = 0; it < 4; it++) {
            const int e = tid + it * 256;            // 0..1023
            const int o = e >> 3, c = e & 7;
            cp16(wh + 2 * SWZ(o * 64 + c * 8), &Wsplit_d[wsel][o][0][kc * 64 + c * 8]);
            cp16(wl + 2 * SWZ(o * 64 + c * 8), &Wsplit_d[wsel][o][1][kc * 64 + c * 8]);
        }
        // X chunk: LDG fp32, split, STS
#pragma unroll
        for (int it = 0; it < 4; it++) {
            const int e = tid + it * 256;            // 0..1023 float4s
            const int row = e >> 4, c4 = e & 15;
            const float4 v = *(const float4*)(X + (size_t)(row0 + row) * 128 + kc * 64 + c4 * 4);
            __half h0, h1, h2, h3, l0, l1, l2, l3;
            split2(v.x, h0, l0); split2(v.y, h1, l1);
            split2(v.z, h2, l2); split2(v.w, h3, l3);
            uint2 hp, lp;
            hp.x = pack2(h0, h1);  hp.y = pack2(h2, h3);
            lp.x = pack2(l0, l1);  lp.y = pack2(l2, l3);
            const uint32_t off = 2 * SWZ(row * 64 + c4 * 4);
            *(uint2*)((char*)Xh + off) = hp;
            *(uint2*)((char*)Xl + off) = lp;
        }
        CP_COMMIT(); CP_WAIT0();
        __syncthreads();

        // MMA: 4 ksteps x 4 o-blocks x (hh + lh + hl)
#pragma unroll
        for (int t = 0; t < 4; t++) {
            uint32_t Ah[4], Al[4];
            const uint32_t arow = mrow0 + (grp & 1) * 8 + wi;
            const uint32_t acol = t * 16 + (grp >> 1) * 8;
            ldm4(Ah, xh + 2 * SWZ(arow * 64 + acol));
            ldm4(Al, xl + 2 * SWZ(arow * 64 + acol));
#pragma unroll
            for (int pb = 0; pb < 4; pb++) {
                const uint32_t orow = ncol0 + pb * 16 + (grp >> 1) * 8 + wi;
                const uint32_t ocol = t * 16 + (grp & 1) * 8;
                uint32_t Bh[4], Bl[4];
                ldm4(Bh, wh + 2 * SWZ(orow * 64 + ocol));
                mma16816(C[2 * pb],     Ah, Bh);
                mma16816(C[2 * pb + 1], Ah, Bh + 2);
                mma16816(C[2 * pb],     Al, Bh);
                mma16816(C[2 * pb + 1], Al, Bh + 2);
                ldm4(Bl, wl + 2 * SWZ(orow * 64 + ocol));
                mma16816(C[2 * pb],     Ah, Bl);
                mma16816(C[2 * pb + 1], Ah, Bl + 2);
            }
        }
    }

    // ---- epilogue: bias, scale, split, scatter to packed layouts ----
    const int bb = row0 >> 11;
#pragma unroll
    for (int half = 0; half < 2; half++) {
        const int row = row0 + mrow0 + (lane >> 2) + half * 8;
        const int s   = row & 2047;
#pragma unroll
        for (int nb = 0; nb < 8; nb++) {
            const int col = ncol0 + nb * 8 + (lane & 3) * 2;
            float y0 = C[nb][2 * half]     + __ldg(bias + col);
            float y1 = C[nb][2 * half + 1] + __ldg(bias + col + 1);
            if (p == 0) { y0 *= 0.25f; y1 *= 0.25f; }
            __half h0, h1, l0, l1;
            split2(y0, h0, l0); split2(y1, h1, l1);
            const int hh = col >> 4, dd = col & 15;
            const size_t bhrow = ((size_t)(bb * H_ + hh) * S_ + s);
            const uint32_t hp = pack2(h0, h1);
            const uint32_t lp = pack2(l0, l1);
            switch (p) {
                case 0:
                    *(uint32_t*)(Qpack_d + bhrow * 64 + dd)      = hp;
                    *(uint32_t*)(Qpack_d + bhrow * 64 + 32 + dd) = lp;
                    break;
                case 1:
                    *(uint32_t*)(Qpack_d + bhrow * 64 + 16 + dd) = hp;
                    *(uint32_t*)(Qpack_d + bhrow * 64 + 48 + dd) = lp;
                    break;
                case 2:
                    *(uint32_t*)(Kpack_d + bhrow * 64 + dd)      = hp;
                    *(uint32_t*)(Kpack_d + bhrow * 64 + 32 + dd) = lp;
                    break;
                case 3:
                    *(uint32_t*)(Kpack_d + bhrow * 64 + 16 + dd) = hp;
                    *(uint32_t*)(Kpack_d + bhrow * 64 + 48 + dd) = lp;
                    break;
                default: {
                    const size_t vi0 = ((size_t)(bb * H_ + hh) * 16 + dd) * S_ + s;
                    const size_t vi1 = ((size_t)(bb * H_ + hh) * 16 + dd + 1) * S_ + s;
                    Vh_d[vi0] = h0; Vh_d[vi1] = h1;
                    Vl_d[vi0] = l0; Vl_d[vi1] = l1;
                } break;
            }
        }
    }
}

// ---------------------------------------------------------------------------
// Kernel 2: HMMA flash attention (unchanged from round 3).
// ---------------------------------------------------------------------------
__global__ void __launch_bounds__(256, 2) flash_kernel()
{
    __shared__ __align__(1024) char Qs[16384];       // 128 rows x [Qh|Ql] 128B
    __shared__ __align__(1024) char Ks[2][8192];     // 64 keys x [Kh|Kl] 128B
    __shared__ __align__(1024) char Vhs[2][2048];    // 16 vd x 64 keys fp16
    __shared__ __align__(1024) char Vls[2][2048];

    const int qt = blockIdx.x;
    const int bh = blockIdx.y;
    const int tid  = threadIdx.x;
    const int warp = tid >> 5;
    const int lane = tid & 31;
    const int grp  = lane >> 3;
    const int wi   = lane & 7;

    const uint32_t qs = smem_u32(Qs);
    const uint32_t ksb[2] = { smem_u32(Ks[0]),  smem_u32(Ks[1]) };
    const uint32_t vhb[2] = { smem_u32(Vhs[0]), smem_u32(Vhs[1]) };
    const uint32_t vlb[2] = { smem_u32(Vls[0]), smem_u32(Vls[1]) };

    {
        const __half* Qg = Qpack_d + ((size_t)bh * S_ + (size_t)qt * 128) * 64;
#pragma unroll
        for (int i = 0; i < 4; i++) {
            int e = tid + i * 256;
            cp16(qs + SWZ((e >> 3) * 128 + (e & 7) * 16), Qg + (size_t)e * 8);
        }
    }
#pragma unroll
    for (int pre = 0; pre < 2; pre++) {
        const __half* Kg = Kpack_d + ((size_t)bh * S_ + (size_t)pre * 64) * 64;
#pragma unroll
        for (int i = 0; i < 2; i++) {
            int e = tid + i * 256;
            cp16(ksb[pre] + SWZ((e >> 3) * 128 + (e & 7) * 16), Kg + (size_t)e * 8);
        }
        if (tid < 128) {
            int r = tid >> 3, c = tid & 7;
            cp16(vhb[pre] + SWZ(r * 128 + c * 16),
                 Vh_d + ((size_t)bh * 16 + r) * S_ + (size_t)pre * 64 + c * 8);
        } else {
            int t2 = tid - 128;
            int r = t2 >> 3, c = t2 & 7;
            cp16(vlb[pre] + SWZ(r * 128 + c * 16),
                 Vl_d + ((size_t)bh * 16 + r) * S_ + (size_t)pre * 64 + c * 8);
        }
        CP_COMMIT();
    }

    CP_WAIT1();
    __syncthreads();

    uint32_t Aq[4][4];
#pragma unroll
    for (int t = 0; t < 4; t++) {
        const int row = warp * 16 + (grp & 1) * 8 + wi;
        const int ch  = t * 16 + (grp >> 1) * 8;
        ldm4(Aq[t], qs + SWZ(row * 128 + ch * 2));
    }

    float m0 = -1e30f, m1 = -1e30f, l0 = 0.f, l1 = 0.f;
    float Oc[2][4];
#pragma unroll
    for (int nb = 0; nb < 2; nb++)
#pragma unroll
        for (int j = 0; j < 4; j++) Oc[nb][j] = 0.f;

    for (int kt = 0; kt < S_ / 64; kt++) {
        const int buf = kt & 1;
        const uint32_t kss = ksb[buf];

        float Sc[8][4];
#pragma unroll
        for (int nb = 0; nb < 8; nb++)
#pragma unroll
            for (int j = 0; j < 4; j++) Sc[nb][j] = 0.f;

#pragma unroll
        for (int t = 0; t < 2; t++) {
#pragma unroll
            for (int p = 0; p < 4; p++) {
                const int key = p * 16 + (grp >> 1) * 8 + wi;
                uint32_t kb[4];
                ldm4(kb, kss + SWZ(key * 128 + (t * 16 + (grp & 1) * 8) * 2));
                mma16816(Sc[2 * p],     Aq[t],     kb);
                mma16816(Sc[2 * p + 1], Aq[t],     kb + 2);
                mma16816(Sc[2 * p],     Aq[t + 2], kb);
                mma16816(Sc[2 * p + 1], Aq[t + 2], kb + 2);
                ldm4(kb, kss + SWZ(key * 128 + (32 + t * 16 + (grp & 1) * 8) * 2));
                mma16816(Sc[2 * p],     Aq[t], kb);
                mma16816(Sc[2 * p + 1], Aq[t], kb + 2);
            }
        }

        float mx0 = -1e30f, mx1 = -1e30f;
#pragma unroll
        for (int nb = 0; nb < 8; nb++) {
            mx0 = fmaxf(mx0, fmaxf(Sc[nb][0], Sc[nb][1]));
            mx1 = fmaxf(mx1, fmaxf(Sc[nb][2], Sc[nb][3]));
        }
        mx0 = fmaxf(mx0, __shfl_xor_sync(0xffffffffu, mx0, 1));
        mx0 = fmaxf(mx0, __shfl_xor_sync(0xffffffffu, mx0, 2));
        mx1 = fmaxf(mx1, __shfl_xor_sync(0xffffffffu, mx1, 1));
        mx1 = fmaxf(mx1, __shfl_xor_sync(0xffffffffu, mx1, 2));

        const float mn0 = fmaxf(m0, mx0), mn1 = fmaxf(m1, mx1);
        const float c0 = __expf(m0 - mn0), c1 = __expf(m1 - mn1);
        m0 = mn0; m1 = mn1;

        float s0 = 0.f, s1 = 0.f;
#pragma unroll
        for (int nb = 0; nb < 8; nb++) {
            Sc[nb][0] = __expf(Sc[nb][0] - mn0);
            Sc[nb][1] = __expf(Sc[nb][1] - mn0);
            Sc[nb][2] = __expf(Sc[nb][2] - mn1);
            Sc[nb][3] = __expf(Sc[nb][3] - mn1);
            s0 += Sc[nb][0] + Sc[nb][1];
            s1 += Sc[nb][2] + Sc[nb][3];
        }
        s0 += __shfl_xor_sync(0xffffffffu, s0, 1);
        s0 += __shfl_xor_sync(0xffffffffu, s0, 2);
        s1 += __shfl_xor_sync(0xffffffffu, s1, 1);
        s1 += __shfl_xor_sync(0xffffffffu, s1, 2);
        l0 = l0 * c0 + s0;
        l1 = l1 * c1 + s1;

#pragma unroll
        for (int nb = 0; nb < 2; nb++) {
            Oc[nb][0] *= c0; Oc[nb][1] *= c0;
            Oc[nb][2] *= c1; Oc[nb][3] *= c1;
        }

        const int vrow = (grp >> 1) * 8 + wi;
#pragma unroll
        for (int k2 = 0; k2 < 4; k2++) {
            uint32_t Pa[4], Pla[4];
#pragma unroll
            for (int h = 0; h < 2; h++) {
                const float e0 = Sc[2 * k2 + h][0], e1 = Sc[2 * k2 + h][1];
                const float e2 = Sc[2 * k2 + h][2], e3 = Sc[2 * k2 + h][3];
                __half2 h01 = __floats2half2_rn(e0, e1);
                __half2 h23 = __floats2half2_rn(e2, e3);
                float2 f01 = __half22float2(h01);
                float2 f23 = __half22float2(h23);
                __half2 l01 = __floats2half2_rn(e0 - f01.x, e1 - f01.y);
                __half2 l23 = __floats2half2_rn(e2 - f23.x, e3 - f23.y);
                Pa[2 * h]      = *reinterpret_cast<uint32_t*>(&h01);
                Pa[2 * h + 1]  = *reinterpret_cast<uint32_t*>(&h23);
                Pla[2 * h]     = *reinterpret_cast<uint32_t*>(&l01);
                Pla[2 * h + 1] = *reinterpret_cast<uint32_t*>(&l23);
            }
            const uint32_t voff = SWZ(vrow * 128 + (k2 * 16 + (grp & 1) * 8) * 2);
            uint32_t vb[4];
            ldm4(vb, vhb[buf] + voff);
            mma16816(Oc[0], Pa,  vb);
            mma16816(Oc[1], Pa,  vb + 2);
            mma16816(Oc[0], Pla, vb);
            mma16816(Oc[1], Pla, vb + 2);
            ldm4(vb, vlb[buf] + voff);
            mma16816(Oc[0], Pa, vb);
            mma16816(Oc[1], Pa, vb + 2);
        }

        __syncthreads();
        if (kt + 2 < S_ / 64) {
            const __half* Kg = Kpack_d + ((size_t)bh * S_ + (size_t)(kt + 2) * 64) * 64;
#pragma unroll
            for (int i = 0; i < 2; i++) {
                int e = tid + i * 256;
                cp16(ksb[buf] + SWZ((e >> 3) * 128 + (e & 7) * 16), Kg + (size_t)e * 8);
            }
            if (tid < 128) {
                int r = tid >> 3, c = tid & 7;
                cp16(vhb[buf] + SWZ(r * 128 + c * 16),
                     Vh_d + ((size_t)bh * 16 + r) * S_ + (size_t)(kt + 2) * 64 + c * 8);
            } else {
                int t2 = tid - 128;
                int r = t2 >> 3, c = t2 & 7;
                cp16(vlb[buf] + SWZ(r * 128 + c * 16),
                     Vl_d + ((size_t)bh * 16 + r) * S_ + (size_t)(kt + 2) * 64 + c * 8);
            }
        }
        CP_COMMIT();
        if (kt + 1 < S_ / 64) {
            CP_WAIT1();
            __syncthreads();
        }
    }

    {
        const float i0 = 1.0f / l0, i1 = 1.0f / l1;
        const int r0 = qt * 128 + warp * 16 + (lane >> 2);
        const int r1 = r0 + 8;
#pragma unroll
        for (int nb = 0; nb < 2; nb++) {
            const int col = nb * 8 + (lane & 3) * 2;
            float2* d0 = (float2*)(Od_d + ((size_t)bh * S_ + r0) * 16 + col);
            float2* d1 = (float2*)(Od_d + ((size_t)bh * S_ + r1) * 16 + col);
            *d0 = make_float2(Oc[nb][0] * i0, Oc[nb][1] * i0);
            *d1 = make_float2(Oc[nb][2] * i1, Oc[nb][3] * i1);
        }
    }
}

// ---------------------------------------------------------------------------
// Kernel 3: HMMA output projection.  out = concat_heads(O) @ Wo^T + bo
// ---------------------------------------------------------------------------
__global__ void __launch_bounds__(256) outproj_kernel(
    const float* __restrict__ bo, float* __restrict__ out)
{
    __shared__ __align__(1024) __half Xh[64 * 64];
    __shared__ __align__(1024) __half Xl[64 * 64];
    __shared__ __align__(1024) __half Wh[128 * 64];
    __shared__ __align__(1024) __half Wl[128 * 64];

    const int row0 = blockIdx.x * 64;
    const int bb = row0 >> 11;
    const int s0 = row0 & 2047;

    const int tid  = threadIdx.x;
    const int warp = tid >> 5;
    const int lane = tid & 31;
    const int grp  = lane >> 3;
    const int wi   = lane & 7;

    const uint32_t xh = smem_u32(Xh), xl = smem_u32(Xl);
    const uint32_t wh = smem_u32(Wh), wl = smem_u32(Wl);

    const int mrow0 = (warp >> 1) * 16;
    const int ncol0 = (warp & 1) * 64;

    float C[8][4];
#pragma unroll
    for (int nb = 0; nb < 8; nb++)
#pragma unroll
        for (int j = 0; j < 4; j++) C[nb][j] = 0.f;

    for (int kc = 0; kc < 2; kc++) {
        __syncthreads();
#pragma unroll
        for (int it = 0; it < 4; it++) {
            const int e = tid + it * 256;
            const int o = e >> 3, c = e & 7;
            cp16(wh + 2 * SWZ(o * 64 + c * 8), &Wsplit_d[3][o][0][kc * 64 + c * 8]);
            cp16(wl + 2 * SWZ(o * 64 + c * 8), &Wsplit_d[3][o][1][kc * 64 + c * 8]);
        }
#pragma unroll
        for (int it = 0; it < 4; it++) {
            const int e = tid + it * 256;
            const int row = e >> 4, c4 = e & 15;
            const int col = kc * 64 + c4 * 4;
            const int hh = col >> 4, dd = col & 15;
            const float4 v = *(const float4*)(Od_d +
                (((size_t)(bb * H_ + hh) * S_) + s0 + row) * 16 + dd);
            __half h0, h1, h2, h3, l0, l1, l2, l3;
            split2(v.x, h0, l0); split2(v.y, h1, l1);
            split2(v.z, h2, l2); split2(v.w, h3, l3);
            uint2 hp, lp;
            hp.x = pack2(h0, h1);  hp.y = pack2(h2, h3);
            lp.x = pack2(l0, l1);  lp.y = pack2(l2, l3);
            const uint32_t off = 2 * SWZ(row * 64 + c4 * 4);
            *(uint2*)((char*)Xh + off) = hp;
            *(uint2*)((char*)Xl + off) = lp;
        }
        CP_COMMIT(); CP_WAIT0();
        __syncthreads();

#pragma unroll
        for (int t = 0; t < 4; t++) {
            uint32_t Ah[4], Al[4];
            const uint32_t arow = mrow0 + (grp & 1) * 8 + wi;
            const uint32_t acol = t * 16 + (grp >> 1) * 8;
            ldm4(Ah, xh + 2 * SWZ(arow * 64 + acol));
            ldm4(Al, xl + 2 * SWZ(arow * 64 + acol));
#pragma unroll
            for (int pb = 0; pb < 4; pb++) {
                const uint32_t orow = ncol0 + pb * 16 + (grp >> 1) * 8 + wi;
                const uint32_t ocol = t * 16 + (grp & 1) * 8;
                uint32_t Bh[4], Bl[4];
                ldm4(Bh, wh + 2 * SWZ(orow * 64 + ocol));
                mma16816(C[2 * pb],     Ah, Bh);
                mma16816(C[2 * pb + 1], Ah, Bh + 2);
                mma16816(C[2 * pb],     Al, Bh);
                mma16816(C[2 * pb + 1], Al, Bh + 2);
                ldm4(Bl, wl + 2 * SWZ(orow * 64 + ocol));
                mma16816(C[2 * pb],     Ah, Bl);
                mma16816(C[2 * pb + 1], Ah, Bl + 2);
            }
        }
    }

#pragma unroll
    for (int half = 0; half < 2; half++) {
        const int row = row0 + mrow0 + (lane >> 2) + half * 8;
#pragma unroll
        for (int nb = 0; nb < 8; nb++) {
            const int col = ncol0 + nb * 8 + (lane & 3) * 2;
            float2* dst = (float2*)(out + (size_t)row * 128 + col);
            *dst = make_float2(C[nb][2 * half]     + __ldg(bo + col),
                               C[nb][2 * half + 1] + __ldg(bo + col + 1));
        }
    }
}

// ---------------------------------------------------------------------------
extern "C" void kernel_launch(void* const* d_in, const int* in_sizes, int n_in,
                              void* d_out, int out_size)
{
    const float* query = (const float*)d_in[0];
    const float* key   = (const float*)d_in[1];
    const float* value = (const float*)d_in[2];
    const float* pos   = (const float*)d_in[3];
    const float* W0    = (const float*)d_in[4];
    const float* b0    = (const float*)d_in[5];
    const float* W1    = (const float*)d_in[6];
    const float* b1    = (const float*)d_in[7];
    const float* W2    = (const float*)d_in[8];
    const float* b2    = (const float*)d_in[9];
    const float* Wo    = (const float*)d_in[10];
    const float* bo    = (const float*)d_in[11];
    float* out = (float*)d_out;

    prep_kernel<<<256, 256>>>(W0, W1, W2, Wo);
    proj_kernel<<<dim3((B_ * S_) / 64, 5), 256>>>(query, key, value, pos, b0, b1, b2);
    flash_kernel<<<dim3(S_ / 128, BH_), 256>>>();
    outproj_kernel<<<(B_ * S_) / 64, 256>>>(bo, out);
}

// round 6
// speedup vs baseline: 3.6665x; 1.3386x over previous
#include <cuda_runtime.h>
#include <cuda_fp16.h>
#include <cstdint>

// Problem constants
#define B_    4
#define S_    2048
#define H_    8
#define BH_   (B_*H_)       // 32

// log2(e) folded into q/pos_q at projection time (softmax in exp2 domain)
#define LOG2E_F      1.4426950408889634f
#define QSCALE_F     0.36067376022224085f   // 0.25 * log2(e)

// Packed split-fp16 intermediates (static device scratch)
__device__ __align__(256) __half Qpack_d[(size_t)BH_ * S_ * 64];  // [bh][s][Qh(32)|Ql(32)]
__device__ __align__(256) __half Kpack_d[(size_t)BH_ * S_ * 64];  // [bh][key][Kh(32)|Kl(32)]
__device__ __align__(256) __half Vh_d[(size_t)BH_ * 16 * S_];     // [bh][vd][key]
__device__ __align__(256) float  Od_d[(size_t)BH_ * S_ * 16];     // [bh][s][16]
__device__ __align__(256) __half Wsplit_d[4][128][2][128];        // [w][o][hi/lo][k]

// ---------------------------------------------------------------------------
// PTX helpers (baseline features only — compute_103-safe)
// ---------------------------------------------------------------------------
__device__ __forceinline__ uint32_t smem_u32(const void* p) {
    uint32_t a;
    asm("{ .reg .u64 t; cvta.to.shared.u64 t, %1; cvt.u32.u64 %0, t; }" : "=r"(a) : "l"(p));
    return a;
}
__device__ __forceinline__ void cp16(uint32_t d, const void* s) {
    asm volatile("cp.async.cg.shared.global [%0], [%1], 16;" :: "r"(d), "l"(s));
}
#define CP_COMMIT() asm volatile("cp.async.commit_group;" ::: "memory")
#define CP_WAIT1()  asm volatile("cp.async.wait_group 1;" ::: "memory")
#define CP_WAIT0()  asm volatile("cp.async.wait_group 0;" ::: "memory")

__device__ __forceinline__ void ldm4(uint32_t* r, uint32_t addr) {
    asm volatile("ldmatrix.sync.aligned.m8n8.x4.shared.b16 {%0,%1,%2,%3}, [%4];"
        : "=r"(r[0]), "=r"(r[1]), "=r"(r[2]), "=r"(r[3]) : "r"(addr));
}
__device__ __forceinline__ void mma16816(float* d, const uint32_t* a, const uint32_t* b) {
    asm volatile("mma.sync.aligned.m16n8k16.row.col.f32.f16.f16.f32 "
        "{%0,%1,%2,%3}, {%4,%5,%6,%7}, {%8,%9}, {%0,%1,%2,%3};"
        : "+f"(d[0]), "+f"(d[1]), "+f"(d[2]), "+f"(d[3])
        : "r"(a[0]), "r"(a[1]), "r"(a[2]), "r"(a[3]), "r"(b[0]), "r"(b[1]));
}
__device__ __forceinline__ float ex2(float x) {
    float y;
    asm("ex2.approx.ftz.f32 %0, %1;" : "=f"(y) : "f"(x));
    return y;
}

#define SWZ(x) ((x) ^ (((x) >> 3) & 0x70))

__device__ __forceinline__ void split2(float x, __half& hi, __half& lo) {
    hi = __float2half_rn(x);
    lo = __float2half_rn(x - __half2float(hi));
}
__device__ __forceinline__ uint32_t pack2(__half a, __half b) {
    __half2 t = __halves2half2(a, b);
    return *reinterpret_cast<uint32_t*>(&t);
}

// ---------------------------------------------------------------------------
// Kernel 0: split W0/W1/W2/Wo into fp16 hi/lo pairs.
// ---------------------------------------------------------------------------
__global__ void __launch_bounds__(256) prep_kernel(
    const float* __restrict__ W0, const float* __restrict__ W1,
    const float* __restrict__ W2, const float* __restrict__ Wo)
{
    const int idx = blockIdx.x * 256 + threadIdx.x;   // 0 .. 65535
    const int w = idx >> 14;
    const int o = (idx >> 7) & 127;
    const int k = idx & 127;
    const float* W = (w == 0) ? W0 : (w == 1) ? W1 : (w == 2) ? W2 : Wo;
    __half hi, lo;
    split2(W[o * 128 + k], hi, lo);
    Wsplit_d[w][o][0][k] = hi;
    Wsplit_d[w][o][1][k] = lo;
}

// ---------------------------------------------------------------------------
// Kernel 1: HMMA projections (split-fp16, 3 chains).
//   p=0: query@W0^T *0.25*log2e -> Q dims 0-15   p=1: pos@W0^T *log2e -> Q dims 16-31
//   p=2: key  @W1^T             -> K dims 0-15   p=3: pos@W1^T        -> K dims 16-31
//   p=4: value@W2^T             -> Vh (transposed, hi only)
// ---------------------------------------------------------------------------
__global__ void __launch_bounds__(256) proj_kernel(
    const float* __restrict__ query, const float* __restrict__ key,
    const float* __restrict__ value, const float* __restrict__ pos,
    const float* __restrict__ b0, const float* __restrict__ b1,
    const float* __restrict__ b2)
{
    __shared__ __align__(1024) __half Xh[64 * 64];    // 64 rows x 128B
    __shared__ __align__(1024) __half Xl[64 * 64];
    __shared__ __align__(1024) __half Wh[128 * 64];   // 128 o x 128B
    __shared__ __align__(1024) __half Wl[128 * 64];

    const int p = blockIdx.y;
    const float* X = (p == 0) ? query : (p == 1 || p == 3) ? pos : (p == 2) ? key : value;
    const float* bias = (p < 2) ? b0 : (p < 4) ? b1 : b2;
    const int wsel = (p < 2) ? 0 : (p < 4) ? 1 : 2;

    const int row0 = blockIdx.x * 64;
    const int tid  = threadIdx.x;
    const int warp = tid >> 5;
    const int lane = tid & 31;
    const int grp  = lane >> 3;
    const int wi   = lane & 7;

    const uint32_t xh = smem_u32(Xh), xl = smem_u32(Xl);
    const uint32_t wh = smem_u32(Wh), wl = smem_u32(Wl);

    const int mrow0 = (warp >> 1) * 16;     // warp row base within tile
    const int ncol0 = (warp & 1) * 64;      // warp col base

    float C[8][4];
#pragma unroll
    for (int nb = 0; nb < 8; nb++)
#pragma unroll
        for (int j = 0; j < 4; j++) C[nb][j] = 0.f;

    for (int kc = 0; kc < 2; kc++) {
        __syncthreads();
#pragma unroll
        for (int it = 0; it < 4; it++) {
            const int e = tid + it * 256;            // 0..1023
            const int o = e >> 3, c = e & 7;
            cp16(wh + 2 * SWZ(o * 64 + c * 8), &Wsplit_d[wsel][o][0][kc * 64 + c * 8]);
            cp16(wl + 2 * SWZ(o * 64 + c * 8), &Wsplit_d[wsel][o][1][kc * 64 + c * 8]);
        }
#pragma unroll
        for (int it = 0; it < 4; it++) {
            const int e = tid + it * 256;            // 0..1023 float4s
            const int row = e >> 4, c4 = e & 15;
            const float4 v = *(const float4*)(X + (size_t)(row0 + row) * 128 + kc * 64 + c4 * 4);
            __half h0, h1, h2, h3, l0, l1, l2, l3;
            split2(v.x, h0, l0); split2(v.y, h1, l1);
            split2(v.z, h2, l2); split2(v.w, h3, l3);
            uint2 hp, lp;
            hp.x = pack2(h0, h1);  hp.y = pack2(h2, h3);
            lp.x = pack2(l0, l1);  lp.y = pack2(l2, l3);
            const uint32_t off = 2 * SWZ(row * 64 + c4 * 4);
            *(uint2*)((char*)Xh + off) = hp;
            *(uint2*)((char*)Xl + off) = lp;
        }
        CP_COMMIT(); CP_WAIT0();
        __syncthreads();

#pragma unroll
        for (int t = 0; t < 4; t++) {
            uint32_t Ah[4], Al[4];
            const uint32_t arow = mrow0 + (grp & 1) * 8 + wi;
            const uint32_t acol = t * 16 + (grp >> 1) * 8;
            ldm4(Ah, xh + 2 * SWZ(arow * 64 + acol));
            ldm4(Al, xl + 2 * SWZ(arow * 64 + acol));
#pragma unroll
            for (int pb = 0; pb < 4; pb++) {
                const uint32_t orow = ncol0 + pb * 16 + (grp >> 1) * 8 + wi;
                const uint32_t ocol = t * 16 + (grp & 1) * 8;
                uint32_t Bh[4], Bl[4];
                ldm4(Bh, wh + 2 * SWZ(orow * 64 + ocol));
                mma16816(C[2 * pb],     Ah, Bh);
                mma16816(C[2 * pb + 1], Ah, Bh + 2);
                mma16816(C[2 * pb],     Al, Bh);
                mma16816(C[2 * pb + 1], Al, Bh + 2);
                ldm4(Bl, wl + 2 * SWZ(orow * 64 + ocol));
                mma16816(C[2 * pb],     Ah, Bl);
                mma16816(C[2 * pb + 1], Ah, Bl + 2);
            }
        }
    }

    // ---- epilogue: bias, scale (log2e folded), split, scatter ----
    const int bb = row0 >> 11;
#pragma unroll
    for (int half = 0; half < 2; half++) {
        const int row = row0 + mrow0 + (lane >> 2) + half * 8;
        const int s   = row & 2047;
#pragma unroll
        for (int nb = 0; nb < 8; nb++) {
            const int col = ncol0 + nb * 8 + (lane & 3) * 2;
            float y0 = C[nb][2 * half]     + __ldg(bias + col);
            float y1 = C[nb][2 * half + 1] + __ldg(bias + col + 1);
            if (p == 0) { y0 *= QSCALE_F; y1 *= QSCALE_F; }
            else if (p == 1) { y0 *= LOG2E_F; y1 *= LOG2E_F; }
            __half h0, h1, l0, l1;
            split2(y0, h0, l0); split2(y1, h1, l1);
            const int hh = col >> 4, dd = col & 15;
            const size_t bhrow = ((size_t)(bb * H_ + hh) * S_ + s);
            const uint32_t hp = pack2(h0, h1);
            const uint32_t lp = pack2(l0, l1);
            switch (p) {
                case 0:
                    *(uint32_t*)(Qpack_d + bhrow * 64 + dd)      = hp;
                    *(uint32_t*)(Qpack_d + bhrow * 64 + 32 + dd) = lp;
                    break;
                case 1:
                    *(uint32_t*)(Qpack_d + bhrow * 64 + 16 + dd) = hp;
                    *(uint32_t*)(Qpack_d + bhrow * 64 + 48 + dd) = lp;
                    break;
                case 2:
                    *(uint32_t*)(Kpack_d + bhrow * 64 + dd)      = hp;
                    *(uint32_t*)(Kpack_d + bhrow * 64 + 32 + dd) = lp;
                    break;
                case 3:
                    *(uint32_t*)(Kpack_d + bhrow * 64 + 16 + dd) = hp;
                    *(uint32_t*)(Kpack_d + bhrow * 64 + 48 + dd) = lp;
                    break;
                default: {
                    const size_t vi0 = ((size_t)(bb * H_ + hh) * 16 + dd) * S_ + s;
                    const size_t vi1 = ((size_t)(bb * H_ + hh) * 16 + dd + 1) * S_ + s;
                    Vh_d[vi0] = h0; Vh_d[vi1] = h1;
                } break;
            }
        }
    }
}

// ---------------------------------------------------------------------------
// Kernel 2: HMMA flash attention.
// QK: 3 chains (hh+lh+hl), 48 mma.  PV: Ph*Vh only, 8 mma.  exp2 domain.
// l accumulated per-lane, reduced across quad once at the end.
// ---------------------------------------------------------------------------
__global__ void __launch_bounds__(256, 2) flash_kernel()
{
    __shared__ __align__(1024) char Qs[16384];       // 128 rows x [Qh|Ql] 128B
    __shared__ __align__(1024) char Ks[2][8192];     // 64 keys x [Kh|Kl] 128B
    __shared__ __align__(1024) char Vhs[2][2048];    // 16 vd x 64 keys fp16

    const int qt = blockIdx.x;
    const int bh = blockIdx.y;
    const int tid  = threadIdx.x;
    const int warp = tid >> 5;
    const int lane = tid & 31;
    const int grp  = lane >> 3;
    const int wi   = lane & 7;

    const uint32_t qs = smem_u32(Qs);
    const uint32_t ksb[2] = { smem_u32(Ks[0]),  smem_u32(Ks[1]) };
    const uint32_t vhb[2] = { smem_u32(Vhs[0]), smem_u32(Vhs[1]) };

    {
        const __half* Qg = Qpack_d + ((size_t)bh * S_ + (size_t)qt * 128) * 64;
#pragma unroll
        for (int i = 0; i < 4; i++) {
            int e = tid + i * 256;
            cp16(qs + SWZ((e >> 3) * 128 + (e & 7) * 16), Qg + (size_t)e * 8);
        }
    }
#pragma unroll
    for (int pre = 0; pre < 2; pre++) {
        const __half* Kg = Kpack_d + ((size_t)bh * S_ + (size_t)pre * 64) * 64;
#pragma unroll
        for (int i = 0; i < 2; i++) {
            int e = tid + i * 256;
            cp16(ksb[pre] + SWZ((e >> 3) * 128 + (e & 7) * 16), Kg + (size_t)e * 8);
        }
        if (tid < 128) {
            int r = tid >> 3, c = tid & 7;
            cp16(vhb[pre] + SWZ(r * 128 + c * 16),
                 Vh_d + ((size_t)bh * 16 + r) * S_ + (size_t)pre * 64 + c * 8);
        }
        CP_COMMIT();
    }

    CP_WAIT1();
    __syncthreads();

    uint32_t Aq[4][4];
#pragma unroll
    for (int t = 0; t < 4; t++) {
        const int row = warp * 16 + (grp & 1) * 8 + wi;
        const int ch  = t * 16 + (grp >> 1) * 8;
        ldm4(Aq[t], qs + SWZ(row * 128 + ch * 2));
    }

    float m0 = -1e30f, m1 = -1e30f, l0 = 0.f, l1 = 0.f;
    float Oc[2][4];
#pragma unroll
    for (int nb = 0; nb < 2; nb++)
#pragma unroll
        for (int j = 0; j < 4; j++) Oc[nb][j] = 0.f;

    for (int kt = 0; kt < S_ / 64; kt++) {
        const int buf = kt & 1;
        const uint32_t kss = ksb[buf];

        float Sc[8][4];
#pragma unroll
        for (int nb = 0; nb < 8; nb++)
#pragma unroll
            for (int j = 0; j < 4; j++) Sc[nb][j] = 0.f;

#pragma unroll
        for (int t = 0; t < 2; t++) {
#pragma unroll
            for (int p = 0; p < 4; p++) {
                const int key = p * 16 + (grp >> 1) * 8 + wi;
                uint32_t kb[4];
                ldm4(kb, kss + SWZ(key * 128 + (t * 16 + (grp & 1) * 8) * 2));
                mma16816(Sc[2 * p],     Aq[t],     kb);
                mma16816(Sc[2 * p + 1], Aq[t],     kb + 2);
                mma16816(Sc[2 * p],     Aq[t + 2], kb);
                mma16816(Sc[2 * p + 1], Aq[t + 2], kb + 2);
                ldm4(kb, kss + SWZ(key * 128 + (32 + t * 16 + (grp & 1) * 8) * 2));
                mma16816(Sc[2 * p],     Aq[t], kb);
                mma16816(Sc[2 * p + 1], Aq[t], kb + 2);
            }
        }

        // --- online softmax (exp2 domain) ---
        float mx0 = -1e30f, mx1 = -1e30f;
#pragma unroll
        for (int nb = 0; nb < 8; nb++) {
            mx0 = fmaxf(mx0, fmaxf(Sc[nb][0], Sc[nb][1]));
            mx1 = fmaxf(mx1, fmaxf(Sc[nb][2], Sc[nb][3]));
        }
        mx0 = fmaxf(mx0, __shfl_xor_sync(0xffffffffu, mx0, 1));
        mx0 = fmaxf(mx0, __shfl_xor_sync(0xffffffffu, mx0, 2));
        mx1 = fmaxf(mx1, __shfl_xor_sync(0xffffffffu, mx1, 1));
        mx1 = fmaxf(mx1, __shfl_xor_sync(0xffffffffu, mx1, 2));

        const float mn0 = fmaxf(m0, mx0), mn1 = fmaxf(m1, mx1);
        const float c0 = ex2(m0 - mn0), c1 = ex2(m1 - mn1);
        m0 = mn0; m1 = mn1;

        float s0 = 0.f, s1 = 0.f;
#pragma unroll
        for (int nb = 0; nb < 8; nb++) {
            Sc[nb][0] = ex2(Sc[nb][0] - mn0);
            Sc[nb][1] = ex2(Sc[nb][1] - mn0);
            Sc[nb][2] = ex2(Sc[nb][2] - mn1);
            Sc[nb][3] = ex2(Sc[nb][3] - mn1);
            s0 += Sc[nb][0] + Sc[nb][1];
            s1 += Sc[nb][2] + Sc[nb][3];
        }
        // deferred: per-lane partial l (quad-reduced once at the end)
        l0 = l0 * c0 + s0;
        l1 = l1 * c1 + s1;

#pragma unroll
        for (int nb = 0; nb < 2; nb++) {
            Oc[nb][0] *= c0; Oc[nb][1] *= c0;
            Oc[nb][2] *= c1; Oc[nb][3] *= c1;
        }

        // --- O += Ph * Vh ---
        const int vrow = (grp >> 1) * 8 + wi;
#pragma unroll
        for (int k2 = 0; k2 < 4; k2++) {
            uint32_t Pa[4];
#pragma unroll
            for (int h = 0; h < 2; h++) {
                __half2 h01 = __floats2half2_rn(Sc[2 * k2 + h][0], Sc[2 * k2 + h][1]);
                __half2 h23 = __floats2half2_rn(Sc[2 * k2 + h][2], Sc[2 * k2 + h][3]);
                Pa[2 * h]     = *reinterpret_cast<uint32_t*>(&h01);
                Pa[2 * h + 1] = *reinterpret_cast<uint32_t*>(&h23);
            }
            uint32_t vb[4];
            ldm4(vb, vhb[buf] + SWZ(vrow * 128 + (k2 * 16 + (grp & 1) * 8) * 2));
            mma16816(Oc[0], Pa, vb);
            mma16816(Oc[1], Pa, vb + 2);
        }

        __syncthreads();
        if (kt + 2 < S_ / 64) {
            const __half* Kg = Kpack_d + ((size_t)bh * S_ + (size_t)(kt + 2) * 64) * 64;
#pragma unroll
            for (int i = 0; i < 2; i++) {
                int e = tid + i * 256;
                cp16(ksb[buf] + SWZ((e >> 3) * 128 + (e & 7) * 16), Kg + (size_t)e * 8);
            }
            if (tid < 128) {
                int r = tid >> 3, c = tid & 7;
                cp16(vhb[buf] + SWZ(r * 128 + c * 16),
                     Vh_d + ((size_t)bh * 16 + r) * S_ + (size_t)(kt + 2) * 64 + c * 8);
            }
        }
        CP_COMMIT();
        if (kt + 1 < S_ / 64) {
            CP_WAIT1();
            __syncthreads();
        }
    }

    {
        // final quad reduction of l
        l0 += __shfl_xor_sync(0xffffffffu, l0, 1);
        l0 += __shfl_xor_sync(0xffffffffu, l0, 2);
        l1 += __shfl_xor_sync(0xffffffffu, l1, 1);
        l1 += __shfl_xor_sync(0xffffffffu, l1, 2);
        const float i0 = 1.0f / l0, i1 = 1.0f / l1;
        const int r0 = qt * 128 + warp * 16 + (lane >> 2);
        const int r1 = r0 + 8;
#pragma unroll
        for (int nb = 0; nb < 2; nb++) {
            const int col = nb * 8 + (lane & 3) * 2;
            float2* d0 = (float2*)(Od_d + ((size_t)bh * S_ + r0) * 16 + col);
            float2* d1 = (float2*)(Od_d + ((size_t)bh * S_ + r1) * 16 + col);
            *d0 = make_float2(Oc[nb][0] * i0, Oc[nb][1] * i0);
            *d1 = make_float2(Oc[nb][2] * i1, Oc[nb][3] * i1);
        }
    }
}

// ---------------------------------------------------------------------------
// Kernel 3: HMMA output projection.  out = concat_heads(O) @ Wo^T + bo
// ---------------------------------------------------------------------------
__global__ void __launch_bounds__(256) outproj_kernel(
    const float* __restrict__ bo, float* __restrict__ out)
{
    __shared__ __align__(1024) __half Xh[64 * 64];
    __shared__ __align__(1024) __half Xl[64 * 64];
    __shared__ __align__(1024) __half Wh[128 * 64];
    __shared__ __align__(1024) __half Wl[128 * 64];

    const int row0 = blockIdx.x * 64;
    const int bb = row0 >> 11;
    const int s0 = row0 & 2047;

    const int tid  = threadIdx.x;
    const int warp = tid >> 5;
    const int lane = tid & 31;
    const int grp  = lane >> 3;
    const int wi   = lane & 7;

    const uint32_t xh = smem_u32(Xh), xl = smem_u32(Xl);
    const uint32_t wh = smem_u32(Wh), wl = smem_u32(Wl);

    const int mrow0 = (warp >> 1) * 16;
    const int ncol0 = (warp & 1) * 64;

    float C[8][4];
#pragma unroll
    for (int nb = 0; nb < 8; nb++)
#pragma unroll
        for (int j = 0; j < 4; j++) C[nb][j] = 0.f;

    for (int kc = 0; kc < 2; kc++) {
        __syncthreads();
#pragma unroll
        for (int it = 0; it < 4; it++) {
            const int e = tid + it * 256;
            const int o = e >> 3, c = e & 7;
            cp16(wh + 2 * SWZ(o * 64 + c * 8), &Wsplit_d[3][o][0][kc * 64 + c * 8]);
            cp16(wl + 2 * SWZ(o * 64 + c * 8), &Wsplit_d[3][o][1][kc * 64 + c * 8]);
        }
#pragma unroll
        for (int it = 0; it < 4; it++) {
            const int e = tid + it * 256;
            const int row = e >> 4, c4 = e & 15;
            const int col = kc * 64 + c4 * 4;
            const int hh = col >> 4, dd = col & 15;
            const float4 v = *(const float4*)(Od_d +
                (((size_t)(bb * H_ + hh) * S_) + s0 + row) * 16 + dd);
            __half h0, h1, h2, h3, l0, l1, l2, l3;
            split2(v.x, h0, l0); split2(v.y, h1, l1);
            split2(v.z, h2, l2); split2(v.w, h3, l3);
            uint2 hp, lp;
            hp.x = pack2(h0, h1);  hp.y = pack2(h2, h3);
            lp.x = pack2(l0, l1);  lp.y = pack2(l2, l3);
            const uint32_t off = 2 * SWZ(row * 64 + c4 * 4);
            *(uint2*)((char*)Xh + off) = hp;
            *(uint2*)((char*)Xl + off) = lp;
        }
        CP_COMMIT(); CP_WAIT0();
        __syncthreads();

#pragma unroll
        for (int t = 0; t < 4; t++) {
            uint32_t Ah[4], Al[4];
            const uint32_t arow = mrow0 + (grp & 1) * 8 + wi;
            const uint32_t acol = t * 16 + (grp >> 1) * 8;
            ldm4(Ah, xh + 2 * SWZ(arow * 64 + acol));
            ldm4(Al, xl + 2 * SWZ(arow * 64 + acol));
#pragma unroll
            for (int pb = 0; pb < 4; pb++) {
                const uint32_t orow = ncol0 + pb * 16 + (grp >> 1) * 8 + wi;
                const uint32_t ocol = t * 16 + (grp & 1) * 8;
                uint32_t Bh[4], Bl[4];
                ldm4(Bh, wh + 2 * SWZ(orow * 64 + ocol));
                mma16816(C[2 * pb],     Ah, Bh);
                mma16816(C[2 * pb + 1], Ah, Bh + 2);
                mma16816(C[2 * pb],     Al, Bh);
                mma16816(C[2 * pb + 1], Al, Bh + 2);
                ldm4(Bl, wl + 2 * SWZ(orow * 64 + ocol));
                mma16816(C[2 * pb],     Ah, Bl);
                mma16816(C[2 * pb + 1], Ah, Bl + 2);
            }
        }
    }

#pragma unroll
    for (int half = 0; half < 2; half++) {
        const int row = row0 + mrow0 + (lane >> 2) + half * 8;
#pragma unroll
        for (int nb = 0; nb < 8; nb++) {
            const int col = ncol0 + nb * 8 + (lane & 3) * 2;
            float2* dst = (float2*)(out + (size_t)row * 128 + col);
            *dst = make_float2(C[nb][2 * half]     + __ldg(bo + col),
                               C[nb][2 * half + 1] + __ldg(bo + col + 1));
        }
    }
}

// ---------------------------------------------------------------------------
extern "C" void kernel_launch(void* const* d_in, const int* in_sizes, int n_in,
                              void* d_out, int out_size)
{
    const float* query = (const float*)d_in[0];
    const float* key   = (const float*)d_in[1];
    const float* value = (const float*)d_in[2];
    const float* pos   = (const float*)d_in[3];
    const float* W0    = (const float*)d_in[4];
    const float* b0    = (const float*)d_in[5];
    const float* W1    = (const float*)d_in[6];
    const float* b1    = (const float*)d_in[7];
    const float* W2    = (const float*)d_in[8];
    const float* b2    = (const float*)d_in[9];
    const float* Wo    = (const float*)d_in[10];
    const float* bo    = (const float*)d_in[11];
    float* out = (float*)d_out;

    prep_kernel<<<256, 256>>>(W0, W1, W2, Wo);
    proj_kernel<<<dim3((B_ * S_) / 64, 5), 256>>>(query, key, value, pos, b0, b1, b2);
    flash_kernel<<<dim3(S_ / 128, BH_), 256>>>();
    outproj_kernel<<<(B_ * S_) / 64, 256>>>(bo, out);
}